// round 10
// baseline (speedup 1.0000x reference)
#include <cuda_runtime.h>

// Problem constants
#define BB   16
#define CIN  8
#define COUT 32
#define HH   64
#define WW   64
#define K2   9
#define NC   8          // spline coefficients per feature
#define NF   9          // features per cin: silu + 8 spline bases
#define TILE 8          // 8x8 spatial tiles
#define THREADS 128

#define FR    10                       // halo rows
#define FCR   10                       // real halo cols
#define FCP   12                       // padded col stride (+swizzle slot)
#define FPIX_S (FR * FCP)              // 120 floats per plane (stored)
#define FPIX_R (FR * FCR)              // 100 real pixels
#define SF_FLOATS (NF * FPIX_S)        // 1080
#define WCHUNK   (NF * K2 * COUT)      // 2592 floats per cin

// Row swizzle: +1 for rows whose pair-index is odd -> warp feature LDS
// spreads across banks (2x2 px blocking makes unswizzled offsets even).
#define SWZ(hr) (((hr) >> 1) & 1)

// Fused weights, computed once per launch by kan_fuse_kernel.
// Layout: gw[c][f][tap][oc], oc fastest.
__device__ float g_fused[CIN * WCHUNK];

__device__ __forceinline__ float silu_f(float x) {
    return x / (1.0f + __expf(-x));
}

// Packed f32x2 FMA: one issue slot, two fp32 FMAs, bit-identical rounding.
__device__ __forceinline__ void ffma2(unsigned long long& d,
                                      unsigned long long a,
                                      unsigned long long b) {
    asm("fma.rn.f32x2 %0, %1, %2, %0;" : "+l"(d) : "l"(a), "l"(b));
}

__device__ __forceinline__ unsigned long long pack2(float v) {
    unsigned long long p;
    asm("mov.b64 %0, {%1, %1};" : "=l"(p) : "f"(v));
    return p;
}

__device__ __forceinline__ void unpack2(unsigned long long p, float& lo, float& hi) {
    asm("mov.b64 {%0, %1}, %2;" : "=f"(lo), "=f"(hi) : "l"(p));
}

// De Boor-Cox recursion, degree 3, uniform knots t[j] = (j-3)*0.4 - 1.0.
// Matches the reference recursion exactly (same formula, fp32).
__device__ __forceinline__ void bspline8(float x, float* __restrict__ out) {
    float t[12];
    #pragma unroll
    for (int j = 0; j < 12; ++j) t[j] = (float)(j - 3) * 0.4f - 1.0f;

    float b[11];
    #pragma unroll
    for (int j = 0; j < 11; ++j)
        b[j] = (x >= t[j] && x < t[j + 1]) ? 1.0f : 0.0f;

    #pragma unroll
    for (int k = 1; k <= 3; ++k) {
        #pragma unroll
        for (int j = 0; j < 10; ++j) {
            if (j < 11 - k) {
                b[j] = (x - t[j]) / (t[j + k] - t[j]) * b[j]
                     + (t[j + k + 1] - x) / (t[j + k + 1] - t[j + 1]) * b[j + 1];
            }
        }
    }
    #pragma unroll
    for (int s = 0; s < NC; ++s) out[s] = b[s];
}

// ---- Kernel A: fuse base/spline weights into g_fused ----
__global__ void kan_fuse_kernel(const float* __restrict__ base_w,
                                const float* __restrict__ spline_w,
                                const float* __restrict__ spline_s)
{
    const int i = blockIdx.x * blockDim.x + threadIdx.x;
    if (i >= CIN * WCHUNK) return;
    const int oc  = i & (COUT - 1);
    const int tap = (i / COUT) % K2;
    const int f   = (i / (COUT * K2)) % NF;
    const int c   = i / WCHUNK;
    const int widx = (oc * CIN + c) * K2 + tap;
    float w;
    if (f == 0) w = base_w[widx];
    else        w = spline_w[widx * NC + (f - 1)] * spline_s[widx];
    g_fused[i] = w;
}

// ---- Kernel B: main conv.
// 1024 CTAs x 128 threads: one balanced resident wave (7 CTAs/SM x 148).
// Thread: ocg = tid >> 4 (8 groups of 4 oc); pxb = tid & 15 -> 2x2 pixel
// block in an 8x8 tile: pr = pxb>>2, pc = pxb&3.
// Warp covers ocg pair (2w, 2w+1) at ADJACENT 16B weight addresses ->
// the two half-warp broadcasts land on disjoint banks = 1 wavefront.
// Double-buffered features/weights, ONE barrier per cin.
__global__ void __launch_bounds__(THREADS, 7)
kan_conv_kernel(const float* __restrict__ x,
                float* __restrict__ out)
{
    __shared__ float sF[2][SF_FLOATS];
    __shared__ float sW[2][WCHUNK];

    const int tid  = threadIdx.x;
    const int tile = blockIdx.x;      // 0..63
    const int b    = blockIdx.y;      // 0..15
    const int th0  = (tile >> 3) * TILE;
    const int tw0  = (tile & 7) * TILE;

    const int ocg = tid >> 4;         // 0..7 (pairs adjacent within a warp)
    const int pxb = tid & 15;
    const int pr  = pxb >> 2;         // 0..3 -> rows 2pr, 2pr+1
    const int pc  = pxb & 3;          // 0..3 -> cols 2pc, 2pc+1

    auto stage_weights = [&](int c, float* dst) {
        const float4* src = reinterpret_cast<const float4*>(g_fused + c * WCHUNK);
        float4* d4 = reinterpret_cast<float4*>(dst);
        #pragma unroll
        for (int k = 0; k < 6; ++k) {
            const int i = tid + k * THREADS;
            if (i < WCHUNK / 4) d4[i] = src[i];
        }
    };
    auto featgen = [&](int c, float* dst) {
        if (tid < FPIX_R) {
            const int hc = tid % FCR;
            const int hr = tid / FCR;
            const int gh = th0 + hr - 1;
            const int gw = tw0 + hc - 1;
            float v = 0.0f;
            if (gh >= 0 && gh < HH && gw >= 0 && gw < WW)
                v = x[((b * CIN + c) * HH + gh) * WW + gw];
            float bs[NC];
            bspline8(v, bs);
            const int o = hr * FCP + hc + SWZ(hr);
            dst[o] = silu_f(v);
            #pragma unroll
            for (int s = 0; s < NC; ++s)
                dst[(s + 1) * FPIX_S + o] = bs[s];
        }
    };

    // Accumulators: 4 px x 4 oc = 16 floats as 8 packed f32x2.
    unsigned long long acc[4][2];
    #pragma unroll
    for (int p = 0; p < 4; ++p) { acc[p][0] = 0ULL; acc[p][1] = 0ULL; }

    // ---- prologue: cin 0 into buffer 0 ----
    stage_weights(0, sW[0]);
    featgen(0, sF[0]);

    for (int c = 0; c < CIN; ++c) {
        const int buf = c & 1;
        __syncthreads();   // buf(c) ready; conv(c-1) done with buf^1

        if (c < CIN - 1) {
            stage_weights(c + 1, sW[1 - buf]);
            featgen(c + 1, sF[1 - buf]);
        }

        const float* __restrict__ sFb = sF[buf];
        const float* __restrict__ sWb = sW[buf];

        #pragma unroll 3
        for (int f = 0; f < NF; ++f) {
            const float* fpl = sFb + f * FPIX_S;

            // rolling window rows: rw[0] = row (2pr+dh), rw[1] = next row
            unsigned long long rw[2][4];
            #pragma unroll
            for (int k = 0; k < 2; ++k) {
                const int row = 2 * pr + k;
                const int base = row * FCP + 2 * pc + SWZ(row);
                #pragma unroll
                for (int wc = 0; wc < 4; ++wc)
                    rw[k][wc] = pack2(fpl[base + wc]);
            }

            const float* wbase = sWb + (f * K2) * COUT + ocg * 4;

            #pragma unroll
            for (int dh = 0; dh < 3; ++dh) {
                #pragma unroll
                for (int dw = 0; dw < 3; ++dw) {
                    const int tap = dh * 3 + dw;
                    const ulonglong2 w = *reinterpret_cast<const ulonglong2*>(
                        wbase + tap * COUT);
                    #pragma unroll
                    for (int i = 0; i < 2; ++i) {
                        #pragma unroll
                        for (int j = 0; j < 2; ++j) {
                            const unsigned long long fv = rw[i][j + dw];
                            ffma2(acc[i * 2 + j][0], fv, w.x);
                            ffma2(acc[i * 2 + j][1], fv, w.y);
                        }
                    }
                }
                // rotate window: bring in row (2pr + dh + 2)
                if (dh < 2) {
                    #pragma unroll
                    for (int wc = 0; wc < 4; ++wc) rw[0][wc] = rw[1][wc];
                    const int row = 2 * pr + dh + 2;
                    const int base = row * FCP + 2 * pc + SWZ(row);
                    #pragma unroll
                    for (int wc = 0; wc < 4; ++wc)
                        rw[1][wc] = pack2(fpl[base + wc]);
                }
            }
        }
    }

    // ---- write out: 2 rows x 2 cols x 4 oc per thread, float2 over cols ----
    const int gh0 = th0 + 2 * pr;
    const int gw0 = tw0 + 2 * pc;
    #pragma unroll
    for (int i = 0; i < 2; ++i) {
        #pragma unroll
        for (int q = 0; q < 2; ++q) {
            const int oc = ocg * 4 + 2 * q;
            float l0, h0, l1, h1;
            unpack2(acc[i * 2 + 0][q], l0, h0);
            unpack2(acc[i * 2 + 1][q], l1, h1);
            float2* p0 = reinterpret_cast<float2*>(
                &out[((b * COUT + oc + 0) * HH + gh0 + i) * WW + gw0]);
            float2* p1 = reinterpret_cast<float2*>(
                &out[((b * COUT + oc + 1) * HH + gh0 + i) * WW + gw0]);
            *p0 = make_float2(l0, l1);
            *p1 = make_float2(h0, h1);
        }
    }
}

extern "C" void kernel_launch(void* const* d_in, const int* in_sizes, int n_in,
                              void* d_out, int out_size) {
    const float* x   = (const float*)d_in[0];
    const float* bw  = (const float*)d_in[1];
    const float* sw  = (const float*)d_in[2];
    const float* ss  = (const float*)d_in[3];
    float* out       = (float*)d_out;

    kan_fuse_kernel<<<(CIN * WCHUNK + 255) / 256, 256>>>(bw, sw, ss);

    // Prefer a large shared-memory carveout so 7 CTAs/SM fit (29.4KB each).
    cudaFuncSetAttribute(kan_conv_kernel,
                         cudaFuncAttributePreferredSharedMemoryCarveout, 100);

    dim3 grid(64, BB);   // 64 spatial tiles x 16 batches = 1024 CTAs x 128 thr
    kan_conv_kernel<<<grid, THREADS>>>(x, out);
}

// round 11
// speedup vs baseline: 1.0870x; 1.0870x over previous
#include <cuda_runtime.h>

// Problem constants
#define BB   16
#define CIN  8
#define COUT 32
#define HH   64
#define WW   64
#define K2   9
#define NC   8          // spline coefficients per feature
#define NF   9          // features per cin: silu + 8 spline bases
#define TILE 16
#define THREADS 512

#define FR    18                       // halo rows
#define FCR   18                       // real halo cols
#define FCP   20                       // padded col stride (+swizzle slot)
#define FPIX_S (FR * FCP)              // 360 floats per plane (stored)
#define FPIX_R (FR * FCR)              // 324 real pixels
#define SF_FLOATS (NF * FPIX_S)        // 3240
#define WCHUNK   (NF * K2 * COUT)      // 2592 floats per cin

#define PH    (HH + 2)                 // 66 padded feature rows
#define PW    (WW + 2)                 // 66 padded feature cols
#define PPIX  (PH * PW)                // 4356

// Row swizzle: +1 for rows whose pair-index is odd -> warp feature LDS
// spreads across all 32 banks (2x2 px blocking makes raw offsets even).
#define SWZ(hr) (((hr) >> 1) & 1)

// Fused weights (kernel A) and precomputed padded features (kernel C).
__device__ float g_fused[CIN * WCHUNK];
__device__ float g_feat[BB * CIN * NF * PPIX];   // ~20 MB

__device__ __forceinline__ float silu_f(float x) {
    return x / (1.0f + __expf(-x));
}

// Packed f32x2 FMA: one issue slot, two fp32 FMAs, bit-identical rounding.
__device__ __forceinline__ void ffma2(unsigned long long& d,
                                      unsigned long long a,
                                      unsigned long long b) {
    asm("fma.rn.f32x2 %0, %1, %2, %0;" : "+l"(d) : "l"(a), "l"(b));
}

__device__ __forceinline__ unsigned long long pack2(float v) {
    unsigned long long p;
    asm("mov.b64 %0, {%1, %1};" : "=l"(p) : "f"(v));
    return p;
}

__device__ __forceinline__ void unpack2(unsigned long long p, float& lo, float& hi) {
    asm("mov.b64 {%0, %1}, %2;" : "=f"(lo), "=f"(hi) : "l"(p));
}

// De Boor-Cox recursion, degree 3, uniform knots t[j] = (j-3)*0.4 - 1.0.
// Matches the reference recursion exactly (same formula, fp32).
__device__ __forceinline__ void bspline8(float x, float* __restrict__ out) {
    float t[12];
    #pragma unroll
    for (int j = 0; j < 12; ++j) t[j] = (float)(j - 3) * 0.4f - 1.0f;

    float b[11];
    #pragma unroll
    for (int j = 0; j < 11; ++j)
        b[j] = (x >= t[j] && x < t[j + 1]) ? 1.0f : 0.0f;

    #pragma unroll
    for (int k = 1; k <= 3; ++k) {
        #pragma unroll
        for (int j = 0; j < 10; ++j) {
            if (j < 11 - k) {
                b[j] = (x - t[j]) / (t[j + k] - t[j]) * b[j]
                     + (t[j + k + 1] - x) / (t[j + k + 1] - t[j + 1]) * b[j + 1];
            }
        }
    }
    #pragma unroll
    for (int s = 0; s < NC; ++s) out[s] = b[s];
}

// ---- Kernel A: fuse base/spline weights into g_fused ----
__global__ void kan_fuse_kernel(const float* __restrict__ base_w,
                                const float* __restrict__ spline_w,
                                const float* __restrict__ spline_s)
{
    const int i = blockIdx.x * blockDim.x + threadIdx.x;
    if (i >= CIN * WCHUNK) return;
    const int oc  = i & (COUT - 1);
    const int tap = (i / COUT) % K2;
    const int f   = (i / (COUT * K2)) % NF;
    const int c   = i / WCHUNK;
    const int widx = (oc * CIN + c) * K2 + tap;
    float w;
    if (f == 0) w = base_w[widx];
    else        w = spline_w[widx * NC + (f - 1)] * spline_s[widx];
    g_fused[i] = w;
}

// ---- Kernel C: precompute padded feature planes.
// g_feat[(b*CIN+c)*NF + f][hp][wp], hp/wp in [0,66): border = features(x=0),
// matching the conv's zero padding.
__global__ void kan_featgen_kernel(const float* __restrict__ x)
{
    const int px = blockIdx.x * blockDim.x + threadIdx.x;
    if (px >= PPIX) return;
    const int bc = blockIdx.y;          // b*CIN + c
    const int hp = px / PW;
    const int wp = px % PW;
    const int gh = hp - 1, gw = wp - 1;
    float v = 0.0f;
    if (gh >= 0 && gh < HH && gw >= 0 && gw < WW)
        v = x[bc * (HH * WW) + gh * WW + gw];
    float bs[NC];
    bspline8(v, bs);
    float* dst = g_feat + (size_t)bc * NF * PPIX + px;
    dst[0] = silu_f(v);
    #pragma unroll
    for (int s = 0; s < NC; ++s)
        dst[(s + 1) * PPIX] = bs[s];
}

// ---- Kernel B: main conv.
// 256 CTAs x 512 threads (R9 config): ocg = tid >> 6 (8 groups of 4 oc);
// pxg = tid & 63 -> 2x2 pixel block: pr = pxg>>3, pc = pxg&7.
// Per tap: 1 broadcast LDS.128 feeds 8 FFMA2 (4 px x 4 oc).
// Features COPIED from g_feat (no bspline here). Double-buffered, 1 barrier/cin.
__global__ void __launch_bounds__(THREADS, 2)
kan_conv_kernel(const float* __restrict__ x,
                float* __restrict__ out)
{
    __shared__ float sF[2][SF_FLOATS];
    __shared__ float sW[2][WCHUNK];

    const int tid  = threadIdx.x;
    const int tile = blockIdx.x;      // 0..15
    const int b    = blockIdx.y;      // 0..15
    const int th0  = (tile >> 2) * TILE;
    const int tw0  = (tile & 3) * TILE;

    const int ocg = tid >> 6;         // 0..7 (warp-uniform)
    const int pxg = tid & 63;
    const int pr  = pxg >> 3;         // 0..7 -> rows 2pr, 2pr+1
    const int pc  = pxg & 7;          // 0..7 -> cols 2pc, 2pc+1

    auto stage_weights = [&](int c, float* dst) {
        const float4* src = reinterpret_cast<const float4*>(g_fused + c * WCHUNK);
        float4* d4 = reinterpret_cast<float4*>(dst);
        #pragma unroll
        for (int k = 0; k < 2; ++k) {
            const int i = tid + k * THREADS;
            if (i < WCHUNK / 4) d4[i] = src[i];
        }
    };
    // Copy 9 x 18x18 feature windows from the padded global planes.
    // Window origin in padded coords = (th0, tw0) (the -1 halo and +1 pad cancel).
    auto featcopy = [&](int c, float* dst) {
        const float* src = g_feat + ((size_t)(b * CIN + c) * NF) * PPIX
                         + th0 * PW + tw0;
        #pragma unroll
        for (int k = 0; k < 6; ++k) {
            const int e = tid + k * THREADS;
            if (e < NF * FPIX_R) {
                const int f  = e / FPIX_R;
                const int px = e % FPIX_R;
                const int hr = px / FCR;
                const int hc = px % FCR;
                dst[f * FPIX_S + hr * FCP + hc + SWZ(hr)] =
                    src[(size_t)f * PPIX + hr * PW + hc];
            }
        }
    };

    // Accumulators: 4 px x 4 oc = 16 floats as 8 packed f32x2.
    unsigned long long acc[4][2];
    #pragma unroll
    for (int p = 0; p < 4; ++p) { acc[p][0] = 0ULL; acc[p][1] = 0ULL; }

    // ---- prologue: cin 0 into buffer 0 ----
    stage_weights(0, sW[0]);
    featcopy(0, sF[0]);

    for (int c = 0; c < CIN; ++c) {
        const int buf = c & 1;
        __syncthreads();   // buf(c) ready; conv(c-1) done with buf^1

        if (c < CIN - 1) {
            stage_weights(c + 1, sW[1 - buf]);
            featcopy(c + 1, sF[1 - buf]);
        }

        const float* __restrict__ sFb = sF[buf];
        const float* __restrict__ sWb = sW[buf];

        #pragma unroll 3
        for (int f = 0; f < NF; ++f) {
            const float* fpl = sFb + f * FPIX_S;

            // rolling window rows: rw[0] = row (2pr+dh), rw[1] = next row
            unsigned long long rw[2][4];
            #pragma unroll
            for (int k = 0; k < 2; ++k) {
                const int row = 2 * pr + k;
                const int base = row * FCP + 2 * pc + SWZ(row);
                #pragma unroll
                for (int wc = 0; wc < 4; ++wc)
                    rw[k][wc] = pack2(fpl[base + wc]);
            }

            const float* wbase = sWb + (f * K2) * COUT + ocg * 4;

            #pragma unroll
            for (int dh = 0; dh < 3; ++dh) {
                #pragma unroll
                for (int dw = 0; dw < 3; ++dw) {
                    const int tap = dh * 3 + dw;
                    const ulonglong2 w = *reinterpret_cast<const ulonglong2*>(
                        wbase + tap * COUT);
                    #pragma unroll
                    for (int i = 0; i < 2; ++i) {
                        #pragma unroll
                        for (int j = 0; j < 2; ++j) {
                            const unsigned long long fv = rw[i][j + dw];
                            ffma2(acc[i * 2 + j][0], fv, w.x);
                            ffma2(acc[i * 2 + j][1], fv, w.y);
                        }
                    }
                }
                // rotate window: bring in row (2pr + dh + 2)
                if (dh < 2) {
                    #pragma unroll
                    for (int wc = 0; wc < 4; ++wc) rw[0][wc] = rw[1][wc];
                    const int row = 2 * pr + dh + 2;
                    const int base = row * FCP + 2 * pc + SWZ(row);
                    #pragma unroll
                    for (int wc = 0; wc < 4; ++wc)
                        rw[1][wc] = pack2(fpl[base + wc]);
                }
            }
        }
    }

    // ---- write out: 2 rows x 2 cols x 4 oc per thread, float2 over cols ----
    const int gh0 = th0 + 2 * pr;
    const int gw0 = tw0 + 2 * pc;
    #pragma unroll
    for (int i = 0; i < 2; ++i) {
        #pragma unroll
        for (int q = 0; q < 2; ++q) {
            const int oc = ocg * 4 + 2 * q;
            float l0, h0, l1, h1;
            unpack2(acc[i * 2 + 0][q], l0, h0);
            unpack2(acc[i * 2 + 1][q], l1, h1);
            float2* p0 = reinterpret_cast<float2*>(
                &out[((b * COUT + oc + 0) * HH + gh0 + i) * WW + gw0]);
            float2* p1 = reinterpret_cast<float2*>(
                &out[((b * COUT + oc + 1) * HH + gh0 + i) * WW + gw0]);
            *p0 = make_float2(l0, l1);
            *p1 = make_float2(h0, h1);
        }
    }
}

extern "C" void kernel_launch(void* const* d_in, const int* in_sizes, int n_in,
                              void* d_out, int out_size) {
    const float* x   = (const float*)d_in[0];
    const float* bw  = (const float*)d_in[1];
    const float* sw  = (const float*)d_in[2];
    const float* ss  = (const float*)d_in[3];
    float* out       = (float*)d_out;

    kan_fuse_kernel<<<(CIN * WCHUNK + 255) / 256, 256>>>(bw, sw, ss);

    dim3 fgrid((PPIX + 255) / 256, BB * CIN);
    kan_featgen_kernel<<<fgrid, 256>>>(x);

    dim3 grid(16, BB);   // 16 spatial tiles x 16 batches = 256 CTAs x 512 thr
    kan_conv_kernel<<<grid, THREADS>>>(x, out);
}

// round 12
// speedup vs baseline: 1.1972x; 1.1014x over previous
#include <cuda_runtime.h>

// Problem constants
#define BB   16
#define CIN  8
#define COUT 32
#define HH   64
#define WW   64
#define K2   9
#define NC   8          // spline coefficients per feature
#define NF   9          // features per cin: silu + 8 spline bases
#define TILE 16
#define THREADS 512

#define FR    18                       // halo rows
#define FCR   18                       // real halo cols
#define FCP   20                       // padded col stride (+swizzle slot)
#define FPIX_S (FR * FCP)              // 360 floats per plane (stored)
#define FPIX_R (FR * FCR)              // 324 real pixels
#define SF_FLOATS (NF * FPIX_S)        // 3240
#define WCHUNK   (NF * K2 * COUT)      // 2592 floats per cin

#define PH    (HH + 2)                 // 66 padded feature rows
#define PW    (WW + 2)                 // 66 padded feature cols
#define PPIX  (PH * PW)                // 4356

// Row swizzle: +1 for rows whose pair-index is odd -> warp feature LDS
// spreads across all 32 banks (2x2 px blocking makes raw offsets even).
#define SWZ(hr) (((hr) >> 1) & 1)

// Fused weights + precomputed padded features (filled by kan_prep_kernel).
__device__ float g_fused[CIN * WCHUNK];
__device__ float g_feat[BB * CIN * NF * PPIX];   // ~20 MB

__device__ __forceinline__ float silu_f(float x) {
    return x / (1.0f + __expf(-x));
}

// Packed f32x2 FMA: one issue slot, two fp32 FMAs, bit-identical rounding.
__device__ __forceinline__ void ffma2(unsigned long long& d,
                                      unsigned long long a,
                                      unsigned long long b) {
    asm("fma.rn.f32x2 %0, %1, %2, %0;" : "+l"(d) : "l"(a), "l"(b));
}

__device__ __forceinline__ unsigned long long pack2(float v) {
    unsigned long long p;
    asm("mov.b64 %0, {%1, %1};" : "=l"(p) : "f"(v));
    return p;
}

__device__ __forceinline__ void unpack2(unsigned long long p, float& lo, float& hi) {
    asm("mov.b64 {%0, %1}, %2;" : "=f"(lo), "=f"(hi) : "l"(p));
}

// De Boor-Cox recursion, degree 3, uniform knots t[j] = (j-3)*0.4 - 1.0.
// Uniform knots => every denominator is exactly k*h; divisions replaced by
// compile-time reciprocal multiplies (deviation ~1e-7, tolerance is 1e-3).
__device__ __forceinline__ void bspline8(float x, float* __restrict__ out) {
    float t[12];
    #pragma unroll
    for (int j = 0; j < 12; ++j) t[j] = (float)(j - 3) * 0.4f - 1.0f;

    float b[11];
    #pragma unroll
    for (int j = 0; j < 11; ++j)
        b[j] = (x >= t[j] && x < t[j + 1]) ? 1.0f : 0.0f;

    #pragma unroll
    for (int k = 1; k <= 3; ++k) {
        const float inv = 1.0f / (0.4f * (float)k);   // 1/(t[j+k]-t[j])
        #pragma unroll
        for (int j = 0; j < 10; ++j) {
            if (j < 11 - k) {
                b[j] = (x - t[j]) * inv * b[j]
                     + (t[j + k + 1] - x) * inv * b[j + 1];
            }
        }
    }
    #pragma unroll
    for (int s = 0; s < NC; ++s) out[s] = b[s];
}

// ---- Kernel A: one launch does BOTH weight fusing and feature precompute.
// blockIdx.y in [0, BB*CIN): featgen for that (b, cin) slice.
// blockIdx.y == BB*CIN     : grid-stride fuse of the 20736 weights.
__global__ void kan_prep_kernel(const float* __restrict__ x,
                                const float* __restrict__ base_w,
                                const float* __restrict__ spline_w,
                                const float* __restrict__ spline_s)
{
    if (blockIdx.y == BB * CIN) {
        // ---- fuse weights into g_fused: gw[c][f][tap][oc] ----
        for (int i = blockIdx.x * blockDim.x + threadIdx.x;
             i < CIN * WCHUNK; i += gridDim.x * blockDim.x) {
            const int oc  = i & (COUT - 1);
            const int tap = (i / COUT) % K2;
            const int f   = (i / (COUT * K2)) % NF;
            const int c   = i / WCHUNK;
            const int widx = (oc * CIN + c) * K2 + tap;
            float w;
            if (f == 0) w = base_w[widx];
            else        w = spline_w[widx * NC + (f - 1)] * spline_s[widx];
            g_fused[i] = w;
        }
        return;
    }

    // ---- featgen: padded planes g_feat[(b*CIN+c)*NF + f][hp][wp] ----
    const int px = blockIdx.x * blockDim.x + threadIdx.x;
    if (px >= PPIX) return;
    const int bc = blockIdx.y;          // b*CIN + c
    const int hp = px / PW;
    const int wp = px % PW;
    const int gh = hp - 1, gw = wp - 1;
    float v = 0.0f;
    if (gh >= 0 && gh < HH && gw >= 0 && gw < WW)
        v = x[bc * (HH * WW) + gh * WW + gw];
    float bs[NC];
    bspline8(v, bs);
    float* dst = g_feat + (size_t)bc * NF * PPIX + px;
    dst[0] = silu_f(v);
    #pragma unroll
    for (int s = 0; s < NC; ++s)
        dst[(s + 1) * PPIX] = bs[s];
}

// ---- Kernel B: main conv (unchanged from R11 winner).
// 256 CTAs x 512 threads: ocg = tid >> 6 (8 groups of 4 oc);
// pxg = tid & 63 -> 2x2 pixel block: pr = pxg>>3, pc = pxg&7.
// Per tap: 1 broadcast LDS.128 feeds 8 FFMA2 (4 px x 4 oc).
// Features COPIED from g_feat. Double-buffered, 1 barrier per cin.
__global__ void __launch_bounds__(THREADS, 2)
kan_conv_kernel(const float* __restrict__ x,
                float* __restrict__ out)
{
    __shared__ float sF[2][SF_FLOATS];
    __shared__ float sW[2][WCHUNK];

    const int tid  = threadIdx.x;
    const int tile = blockIdx.x;      // 0..15
    const int b    = blockIdx.y;      // 0..15
    const int th0  = (tile >> 2) * TILE;
    const int tw0  = (tile & 3) * TILE;

    const int ocg = tid >> 6;         // 0..7 (warp-uniform)
    const int pxg = tid & 63;
    const int pr  = pxg >> 3;         // 0..7 -> rows 2pr, 2pr+1
    const int pc  = pxg & 7;          // 0..7 -> cols 2pc, 2pc+1

    auto stage_weights = [&](int c, float* dst) {
        const float4* src = reinterpret_cast<const float4*>(g_fused + c * WCHUNK);
        float4* d4 = reinterpret_cast<float4*>(dst);
        #pragma unroll
        for (int k = 0; k < 2; ++k) {
            const int i = tid + k * THREADS;
            if (i < WCHUNK / 4) d4[i] = src[i];
        }
    };
    // Copy 9 x 18x18 feature windows from the padded global planes.
    auto featcopy = [&](int c, float* dst) {
        const float* src = g_feat + ((size_t)(b * CIN + c) * NF) * PPIX
                         + th0 * PW + tw0;
        #pragma unroll
        for (int k = 0; k < 6; ++k) {
            const int e = tid + k * THREADS;
            if (e < NF * FPIX_R) {
                const int f  = e / FPIX_R;
                const int px = e % FPIX_R;
                const int hr = px / FCR;
                const int hc = px % FCR;
                dst[f * FPIX_S + hr * FCP + hc + SWZ(hr)] =
                    src[(size_t)f * PPIX + hr * PW + hc];
            }
        }
    };

    // Accumulators: 4 px x 4 oc = 16 floats as 8 packed f32x2.
    unsigned long long acc[4][2];
    #pragma unroll
    for (int p = 0; p < 4; ++p) { acc[p][0] = 0ULL; acc[p][1] = 0ULL; }

    // ---- prologue: cin 0 into buffer 0 ----
    stage_weights(0, sW[0]);
    featcopy(0, sF[0]);

    for (int c = 0; c < CIN; ++c) {
        const int buf = c & 1;
        __syncthreads();   // buf(c) ready; conv(c-1) done with buf^1

        if (c < CIN - 1) {
            stage_weights(c + 1, sW[1 - buf]);
            featcopy(c + 1, sF[1 - buf]);
        }

        const float* __restrict__ sFb = sF[buf];
        const float* __restrict__ sWb = sW[buf];

        #pragma unroll 3
        for (int f = 0; f < NF; ++f) {
            const float* fpl = sFb + f * FPIX_S;

            // rolling window rows: rw[0] = row (2pr+dh), rw[1] = next row
            unsigned long long rw[2][4];
            #pragma unroll
            for (int k = 0; k < 2; ++k) {
                const int row = 2 * pr + k;
                const int base = row * FCP + 2 * pc + SWZ(row);
                #pragma unroll
                for (int wc = 0; wc < 4; ++wc)
                    rw[k][wc] = pack2(fpl[base + wc]);
            }

            const float* wbase = sWb + (f * K2) * COUT + ocg * 4;

            #pragma unroll
            for (int dh = 0; dh < 3; ++dh) {
                #pragma unroll
                for (int dw = 0; dw < 3; ++dw) {
                    const int tap = dh * 3 + dw;
                    const ulonglong2 w = *reinterpret_cast<const ulonglong2*>(
                        wbase + tap * COUT);
                    #pragma unroll
                    for (int i = 0; i < 2; ++i) {
                        #pragma unroll
                        for (int j = 0; j < 2; ++j) {
                            const unsigned long long fv = rw[i][j + dw];
                            ffma2(acc[i * 2 + j][0], fv, w.x);
                            ffma2(acc[i * 2 + j][1], fv, w.y);
                        }
                    }
                }
                // rotate window: bring in row (2pr + dh + 2)
                if (dh < 2) {
                    #pragma unroll
                    for (int wc = 0; wc < 4; ++wc) rw[0][wc] = rw[1][wc];
                    const int row = 2 * pr + dh + 2;
                    const int base = row * FCP + 2 * pc + SWZ(row);
                    #pragma unroll
                    for (int wc = 0; wc < 4; ++wc)
                        rw[1][wc] = pack2(fpl[base + wc]);
                }
            }
        }
    }

    // ---- write out: 2 rows x 2 cols x 4 oc per thread, float2 over cols ----
    const int gh0 = th0 + 2 * pr;
    const int gw0 = tw0 + 2 * pc;
    #pragma unroll
    for (int i = 0; i < 2; ++i) {
        #pragma unroll
        for (int q = 0; q < 2; ++q) {
            const int oc = ocg * 4 + 2 * q;
            float l0, h0, l1, h1;
            unpack2(acc[i * 2 + 0][q], l0, h0);
            unpack2(acc[i * 2 + 1][q], l1, h1);
            float2* p0 = reinterpret_cast<float2*>(
                &out[((b * COUT + oc + 0) * HH + gh0 + i) * WW + gw0]);
            float2* p1 = reinterpret_cast<float2*>(
                &out[((b * COUT + oc + 1) * HH + gh0 + i) * WW + gw0]);
            *p0 = make_float2(l0, l1);
            *p1 = make_float2(h0, h1);
        }
    }
}

extern "C" void kernel_launch(void* const* d_in, const int* in_sizes, int n_in,
                              void* d_out, int out_size) {
    const float* x   = (const float*)d_in[0];
    const float* bw  = (const float*)d_in[1];
    const float* sw  = (const float*)d_in[2];
    const float* ss  = (const float*)d_in[3];
    float* out       = (float*)d_out;

    // One prep launch: featgen (y < BB*CIN) + weight fuse (y == BB*CIN).
    dim3 pgrid((PPIX + 255) / 256, BB * CIN + 1);
    kan_prep_kernel<<<pgrid, 256>>>(x, bw, sw, ss);

    dim3 grid(16, BB);   // 16 spatial tiles x 16 batches = 256 CTAs x 512 thr
    kan_conv_kernel<<<grid, THREADS>>>(x, out);
}